// round 9
// baseline (speedup 1.0000x reference)
#include <cuda_runtime.h>
#include <math.h>

// ---------------- problem constants ----------------
#define BQ     2
#define LQ     1024
#define DQ     256
#define NLQ    4
#define DINQ   512
#define HQ     8
#define PQ     64
#define NSQ    64
#define CONVD  640           // DIN + 2*NSTATE
#define DPROJ  1160          // 2*DIN + 2*NSTATE + H
#define NCH    32            // chunks
#define LC     32            // chunk length (LQ / NCH)

typedef unsigned long long u64;

// packed fp32x2 helpers (sm_100+): one instr = two fp32 FMAs, exact fp32 math
__device__ __forceinline__ u64 pk2(float lo, float hi){
    u64 r; asm("mov.b64 %0, {%1, %2};" : "=l"(r) : "f"(lo), "f"(hi)); return r;
}
__device__ __forceinline__ void upk2(float& lo, float& hi, u64 v){
    asm("mov.b64 {%0, %1}, %2;" : "=f"(lo), "=f"(hi) : "l"(v));
}
__device__ __forceinline__ u64 fma2(u64 a, u64 b, u64 c){
    u64 d; asm("fma.rn.f32x2 %0, %1, %2, %3;" : "=l"(d) : "l"(a), "l"(b), "l"(c)); return d;
}
__device__ __forceinline__ u64 mul2(u64 a, u64 b){
    u64 d; asm("mul.rn.f32x2 %0, %1, %2;" : "=l"(d) : "l"(a), "l"(b)); return d;
}

// ---------------- scratch (device globals; no allocation) ----------------
static __device__ float g_x  [BQ*LQ*DQ];
static __device__ float g_zx [BQ*LQ*DPROJ];
static __device__ float g_xBC[BQ*LQ*CONVD];
static __device__ float g_dt [BQ*LQ*HQ];
static __device__ float g_slast[BQ*HQ*NCH];              // per-chunk S_last
static __device__ float g_y  [BQ*LQ*DINQ];
static __device__ float g_F  [BQ*HQ*NCH*PQ*NSQ];         // chunk-final local state [blk][n][p]
static __device__ float g_Hs [BQ*HQ*NCH*PQ*NSQ];         // chunk-START state H0   [blk][n][p]
static __device__ float g_pool[BQ*DQ];

__device__ __forceinline__ float geluf(float x){
    return 0.5f * x * (1.0f + erff(x * 0.7071067811865476f));
}

// ---------------- embedding ----------------
__global__ void k_embed(const int* __restrict__ ids, const float* __restrict__ emb,
                        const float* __restrict__ pos){
    int row = blockIdx.x;            // b*LQ + l
    int l   = row & (LQ-1);
    int d   = threadIdx.x;
    g_x[(size_t)row*DQ + d] = emb[(size_t)ids[row]*DQ + d] + pos[(size_t)l*DQ + d];
}

// ======== GEMM 128x64, 128 threads, 8x8 micro-tile (balanced smem:fma) ========
// C[m,n] (+)= sum_k A[m,k]*B[n,k]
template<int M, int N, int K, bool ACC>
__device__ __forceinline__ void gemm128x64(const float* __restrict__ A,
                                           const float* __restrict__ Bw,
                                           float* __restrict__ Cc){
    constexpr int BM=128, BN=64, BK=16;
    __shared__ __align__(16) float As[2][BK][BM];
    __shared__ __align__(16) float Bs[2][BK][BN];
    const int tid = threadIdx.x;           // 0..127
    const int bm  = blockIdx.y * BM;
    const int bn  = blockIdx.x * BN;
    const int mg  = (tid >> 3) * 8;        // 8 rows (broadcast within 8-lane groups)
    const int ng  = (tid & 7) * 8;         // 8 cols
    const int brow = tid & 63;
    const int bkh  = (tid >> 6) * 8;

    const bool bvalid = (N % BN == 0) || (bn + brow < N);
    const float* Aptr = A  + (size_t)(bm + tid)*K;
    const float* Bptr = Bw + (size_t)(bn + brow)*K + bkh;

    u64 acc[4][8];
    #pragma unroll
    for (int i=0;i<4;i++)
        #pragma unroll
        for (int j=0;j<8;j++) acc[i][j]=0ull;

    float4 ra0,ra1,ra2,ra3, rb0,rb1;
    auto ldg = [&](int k0){
        ra0 = *(const float4*)(Aptr + k0);
        ra1 = *(const float4*)(Aptr + k0 + 4);
        ra2 = *(const float4*)(Aptr + k0 + 8);
        ra3 = *(const float4*)(Aptr + k0 + 12);
        rb0 = make_float4(0.f,0.f,0.f,0.f);
        rb1 = rb0;
        if (bvalid){
            rb0 = *(const float4*)(Bptr + k0);
            rb1 = *(const float4*)(Bptr + k0 + 4);
        }
    };
    auto sts = [&](int buf){
        As[buf][ 0][tid]=ra0.x; As[buf][ 1][tid]=ra0.y; As[buf][ 2][tid]=ra0.z; As[buf][ 3][tid]=ra0.w;
        As[buf][ 4][tid]=ra1.x; As[buf][ 5][tid]=ra1.y; As[buf][ 6][tid]=ra1.z; As[buf][ 7][tid]=ra1.w;
        As[buf][ 8][tid]=ra2.x; As[buf][ 9][tid]=ra2.y; As[buf][10][tid]=ra2.z; As[buf][11][tid]=ra2.w;
        As[buf][12][tid]=ra3.x; As[buf][13][tid]=ra3.y; As[buf][14][tid]=ra3.z; As[buf][15][tid]=ra3.w;
        Bs[buf][bkh+0][brow]=rb0.x; Bs[buf][bkh+1][brow]=rb0.y;
        Bs[buf][bkh+2][brow]=rb0.z; Bs[buf][bkh+3][brow]=rb0.w;
        Bs[buf][bkh+4][brow]=rb1.x; Bs[buf][bkh+5][brow]=rb1.y;
        Bs[buf][bkh+6][brow]=rb1.z; Bs[buf][bkh+7][brow]=rb1.w;
    };

    ldg(0); sts(0);
    __syncthreads();
    constexpr int NK = K/BK;
    #pragma unroll 1
    for (int kt=0; kt<NK; kt++){
        if (kt+1 < NK) ldg((kt+1)*BK);
        const int cur = kt & 1;
        #pragma unroll
        for (int kk=0; kk<BK; kk++){
            u64 a0 = *(const u64*)&As[cur][kk][mg];
            u64 a1 = *(const u64*)&As[cur][kk][mg+2];
            u64 a2 = *(const u64*)&As[cur][kk][mg+4];
            u64 a3 = *(const u64*)&As[cur][kk][mg+6];
            float4 b0 = *(const float4*)&Bs[cur][kk][ng];
            float4 b1 = *(const float4*)&Bs[cur][kk][ng+4];
            u64 t;
            t = pk2(b0.x,b0.x);
            acc[0][0]=fma2(a0,t,acc[0][0]); acc[1][0]=fma2(a1,t,acc[1][0]);
            acc[2][0]=fma2(a2,t,acc[2][0]); acc[3][0]=fma2(a3,t,acc[3][0]);
            t = pk2(b0.y,b0.y);
            acc[0][1]=fma2(a0,t,acc[0][1]); acc[1][1]=fma2(a1,t,acc[1][1]);
            acc[2][1]=fma2(a2,t,acc[2][1]); acc[3][1]=fma2(a3,t,acc[3][1]);
            t = pk2(b0.z,b0.z);
            acc[0][2]=fma2(a0,t,acc[0][2]); acc[1][2]=fma2(a1,t,acc[1][2]);
            acc[2][2]=fma2(a2,t,acc[2][2]); acc[3][2]=fma2(a3,t,acc[3][2]);
            t = pk2(b0.w,b0.w);
            acc[0][3]=fma2(a0,t,acc[0][3]); acc[1][3]=fma2(a1,t,acc[1][3]);
            acc[2][3]=fma2(a2,t,acc[2][3]); acc[3][3]=fma2(a3,t,acc[3][3]);
            t = pk2(b1.x,b1.x);
            acc[0][4]=fma2(a0,t,acc[0][4]); acc[1][4]=fma2(a1,t,acc[1][4]);
            acc[2][4]=fma2(a2,t,acc[2][4]); acc[3][4]=fma2(a3,t,acc[3][4]);
            t = pk2(b1.y,b1.y);
            acc[0][5]=fma2(a0,t,acc[0][5]); acc[1][5]=fma2(a1,t,acc[1][5]);
            acc[2][5]=fma2(a2,t,acc[2][5]); acc[3][5]=fma2(a3,t,acc[3][5]);
            t = pk2(b1.z,b1.z);
            acc[0][6]=fma2(a0,t,acc[0][6]); acc[1][6]=fma2(a1,t,acc[1][6]);
            acc[2][6]=fma2(a2,t,acc[2][6]); acc[3][6]=fma2(a3,t,acc[3][6]);
            t = pk2(b1.w,b1.w);
            acc[0][7]=fma2(a0,t,acc[0][7]); acc[1][7]=fma2(a1,t,acc[1][7]);
            acc[2][7]=fma2(a2,t,acc[2][7]); acc[3][7]=fma2(a3,t,acc[3][7]);
        }
        if (kt+1 < NK) sts((kt+1) & 1);
        __syncthreads();
    }

    const int col0 = bn + ng;
    const bool cvalid = (N % BN == 0) || (col0 + 8 <= N);   // N % 8 == 0 holds for 1160
    if (cvalid){
        #pragma unroll
        for (int mp=0; mp<4; mp++){
            float4 lo0, lo1, hi0, hi1;
            upk2(lo0.x, hi0.x, acc[mp][0]); upk2(lo0.y, hi0.y, acc[mp][1]);
            upk2(lo0.z, hi0.z, acc[mp][2]); upk2(lo0.w, hi0.w, acc[mp][3]);
            upk2(lo1.x, hi1.x, acc[mp][4]); upk2(lo1.y, hi1.y, acc[mp][5]);
            upk2(lo1.z, hi1.z, acc[mp][6]); upk2(lo1.w, hi1.w, acc[mp][7]);
            size_t r0 = (size_t)(bm + mg + 2*mp)*N + col0;
            size_t r1 = r0 + N;
            if (ACC){
                float4 c;
                c = *(float4*)&Cc[r0];   c.x+=lo0.x; c.y+=lo0.y; c.z+=lo0.z; c.w+=lo0.w; *(float4*)&Cc[r0]   = c;
                c = *(float4*)&Cc[r0+4]; c.x+=lo1.x; c.y+=lo1.y; c.z+=lo1.z; c.w+=lo1.w; *(float4*)&Cc[r0+4] = c;
                c = *(float4*)&Cc[r1];   c.x+=hi0.x; c.y+=hi0.y; c.z+=hi0.z; c.w+=hi0.w; *(float4*)&Cc[r1]   = c;
                c = *(float4*)&Cc[r1+4]; c.x+=hi1.x; c.y+=hi1.y; c.z+=hi1.z; c.w+=hi1.w; *(float4*)&Cc[r1+4] = c;
            } else {
                *(float4*)&Cc[r0]   = lo0;
                *(float4*)&Cc[r0+4] = lo1;
                *(float4*)&Cc[r1]   = hi0;
                *(float4*)&Cc[r1+4] = hi1;
            }
        }
    }
}

// ======== GEMM 64x64, 128 threads, 8x4 micro-tile ========
template<int M, int N, int K, bool ACC>
__device__ __forceinline__ void gemm64x64(const float* __restrict__ A,
                                          const float* __restrict__ Bw,
                                          float* __restrict__ Cc){
    constexpr int BM=64, BN=64, BK=16;
    __shared__ __align__(16) float As[2][BK][BM];
    __shared__ __align__(16) float Bs[2][BK][BN];
    const int tid = threadIdx.x;           // 0..127
    const int bm  = blockIdx.y * BM;
    const int bn  = blockIdx.x * BN;
    const int mg  = (tid >> 4) * 8;        // 8 rows, broadcast within 16-lane groups
    const int ng  = (tid & 15) * 4;        // 4 cols, contiguous across lanes
    const int lrow = tid & 63;
    const int lkh  = (tid >> 6) * 8;

    const bool bvalid = (N % BN == 0) || (bn + lrow < N);
    const float* Aptr = A  + (size_t)(bm + lrow)*K + lkh;
    const float* Bptr = Bw + (size_t)(bn + lrow)*K + lkh;

    u64 acc[4][4];
    #pragma unroll
    for (int i=0;i<4;i++)
        #pragma unroll
        for (int j=0;j<4;j++) acc[i][j]=0ull;

    float4 ra0,ra1, rb0,rb1;
    auto ldg = [&](int k0){
        ra0 = *(const float4*)(Aptr + k0);
        ra1 = *(const float4*)(Aptr + k0 + 4);
        rb0 = make_float4(0.f,0.f,0.f,0.f);
        rb1 = rb0;
        if (bvalid){
            rb0 = *(const float4*)(Bptr + k0);
            rb1 = *(const float4*)(Bptr + k0 + 4);
        }
    };
    auto sts = [&](int buf){
        As[buf][lkh+0][lrow]=ra0.x; As[buf][lkh+1][lrow]=ra0.y;
        As[buf][lkh+2][lrow]=ra0.z; As[buf][lkh+3][lrow]=ra0.w;
        As[buf][lkh+4][lrow]=ra1.x; As[buf][lkh+5][lrow]=ra1.y;
        As[buf][lkh+6][lrow]=ra1.z; As[buf][lkh+7][lrow]=ra1.w;
        Bs[buf][lkh+0][lrow]=rb0.x; Bs[buf][lkh+1][lrow]=rb0.y;
        Bs[buf][lkh+2][lrow]=rb0.z; Bs[buf][lkh+3][lrow]=rb0.w;
        Bs[buf][lkh+4][lrow]=rb1.x; Bs[buf][lkh+5][lrow]=rb1.y;
        Bs[buf][lkh+6][lrow]=rb1.z; Bs[buf][lkh+7][lrow]=rb1.w;
    };

    ldg(0); sts(0);
    __syncthreads();
    constexpr int NK = K/BK;
    #pragma unroll 1
    for (int kt=0; kt<NK; kt++){
        if (kt+1 < NK) ldg((kt+1)*BK);
        const int cur = kt & 1;
        #pragma unroll
        for (int kk=0; kk<BK; kk++){
            u64 a0 = *(const u64*)&As[cur][kk][mg];
            u64 a1 = *(const u64*)&As[cur][kk][mg+2];
            u64 a2 = *(const u64*)&As[cur][kk][mg+4];
            u64 a3 = *(const u64*)&As[cur][kk][mg+6];
            float4 b = *(const float4*)&Bs[cur][kk][ng];
            u64 t;
            t = pk2(b.x,b.x);
            acc[0][0]=fma2(a0,t,acc[0][0]); acc[1][0]=fma2(a1,t,acc[1][0]);
            acc[2][0]=fma2(a2,t,acc[2][0]); acc[3][0]=fma2(a3,t,acc[3][0]);
            t = pk2(b.y,b.y);
            acc[0][1]=fma2(a0,t,acc[0][1]); acc[1][1]=fma2(a1,t,acc[1][1]);
            acc[2][1]=fma2(a2,t,acc[2][1]); acc[3][1]=fma2(a3,t,acc[3][1]);
            t = pk2(b.z,b.z);
            acc[0][2]=fma2(a0,t,acc[0][2]); acc[1][2]=fma2(a1,t,acc[1][2]);
            acc[2][2]=fma2(a2,t,acc[2][2]); acc[3][2]=fma2(a3,t,acc[3][2]);
            t = pk2(b.w,b.w);
            acc[0][3]=fma2(a0,t,acc[0][3]); acc[1][3]=fma2(a1,t,acc[1][3]);
            acc[2][3]=fma2(a2,t,acc[2][3]); acc[3][3]=fma2(a3,t,acc[3][3]);
        }
        if (kt+1 < NK) sts((kt+1) & 1);
        __syncthreads();
    }

    const int col0 = bn + ng;
    const bool cvalid = (N % BN == 0) || (col0 + 4 <= N);
    if (cvalid){
        #pragma unroll
        for (int mp=0; mp<4; mp++){
            float4 lo, hi;
            upk2(lo.x, hi.x, acc[mp][0]);
            upk2(lo.y, hi.y, acc[mp][1]);
            upk2(lo.z, hi.z, acc[mp][2]);
            upk2(lo.w, hi.w, acc[mp][3]);
            size_t i0 = (size_t)(bm + mg + 2*mp)*N + col0;
            size_t i1 = i0 + N;
            if (ACC){
                float4 c;
                c = *(float4*)&Cc[i0]; c.x+=lo.x; c.y+=lo.y; c.z+=lo.z; c.w+=lo.w; *(float4*)&Cc[i0] = c;
                c = *(float4*)&Cc[i1]; c.x+=hi.x; c.y+=hi.y; c.z+=hi.z; c.w+=hi.w; *(float4*)&Cc[i1] = c;
            } else {
                *(float4*)&Cc[i0] = lo;
                *(float4*)&Cc[i1] = hi;
            }
        }
    }
}

__global__ __launch_bounds__(128, 4) void k_gemm_in(const float* __restrict__ W){
    gemm128x64<BQ*LQ, DPROJ, DQ, false>(g_x, W, g_zx);
}
__global__ __launch_bounds__(128) void k_gemm_out(const float* __restrict__ W){
    gemm64x64<BQ*LQ, DQ, DINQ, true>(g_y, W, g_x);
}

// ---------------- depthwise causal conv + SiLU, and dt ----------------
__global__ void k_convdt(const float* __restrict__ cw, const float* __restrict__ cb,
                         const float* __restrict__ dtb){
    int row = blockIdx.x;            // b*LQ + l
    int l   = row & (LQ-1);
    int ci  = threadIdx.x;           // 0..639
    float4 w = *(const float4*)(cw + ci*4);   // conv_w[ci][0..3]
    const float* src = g_zx + (size_t)row*DPROJ + DINQ + ci;
    float acc = cb[ci];
    acc = fmaf(w.w, src[0], acc);
    if (l >= 1) acc = fmaf(w.z, src[-DPROJ],   acc);
    if (l >= 2) acc = fmaf(w.y, src[-2*DPROJ], acc);
    if (l >= 3) acc = fmaf(w.x, src[-3*DPROJ], acc);
    g_xBC[(size_t)row*CONVD + ci] = acc / (1.f + expf(-acc));   // SiLU
    if (ci < HQ){
        float raw = g_zx[(size_t)row*DPROJ + (DINQ + CONVD) + ci] + dtb[ci];
        float dt  = (raw > 20.f) ? raw : log1pf(expf(raw));     // softplus
        g_dt[(size_t)row*HQ + ci] = dt;
    }
}

// ---------------- S1: per-chunk local final state F[n][p] (+ fused warp-scan) ---------
// p contiguous across lanes -> coalesced float4 stores of g_F
__global__ __launch_bounds__(256) void k_state(const float* __restrict__ Alog){
    const int blk = blockIdx.x;
    const int c   = blk & (NCH-1);
    const int bh  = blk >> 5;
    const int h   = bh & (HQ-1);
    const int b   = bh >> 3;
    const int tid = threadIdx.x;
    const int t0  = c*LC;

    __shared__ __align__(16) float sX[LC][PQ];
    __shared__ __align__(16) float sB[LC][NSQ];
    __shared__ float sW[LC];

    for (int idx=tid; idx<LC*128; idx+=256){
        int s = idx >> 7, j = idx & 127;
        const float* rowp = g_xBC + (size_t)(b*LQ + t0 + s)*CONVD;
        if (j < 64) sX[s][j]    = rowp[h*PQ + j];
        else        sB[s][j-64] = rowp[DINQ + (j-64)];
    }
    if (tid < 32){   // chunk-local inclusive cumsum of dt*|A| via warp scan
        float dts  = g_dt[(size_t)(b*LQ + t0 + tid)*HQ + h];
        float v = dts * expf(Alog[h]);
        #pragma unroll
        for (int o=1; o<32; o<<=1){
            float u = __shfl_up_sync(0xffffffffu, v, o);
            if (tid >= o) v += u;
        }
        float Sl = __shfl_sync(0xffffffffu, v, 31);
        sW[tid] = expf(v - Sl) * dts;
        if (tid == 31) g_slast[blk] = v;
    }
    __syncthreads();

    const int p0 = (tid & 15) * 4;     // p contiguous across lanes
    const int n0 = (tid >> 4) * 4;     // n broadcast within half-warp
    u64 fp[2][4];                       // [p-pair][n]
    #pragma unroll
    for (int i=0;i<2;i++)
        #pragma unroll
        for (int j=0;j<4;j++) fp[i][j]=0ull;

    #pragma unroll 4
    for (int s=0; s<LC; s++){
        u64 x01 = *(const u64*)&sX[s][p0];
        u64 x23 = *(const u64*)&sX[s][p0+2];
        float4 bv = *(const float4*)&sB[s][n0];
        float w = sW[s];
        u64 w2 = pk2(w,w);
        u64 wx01 = mul2(x01, w2);
        u64 wx23 = mul2(x23, w2);
        u64 b0 = pk2(bv.x,bv.x), b1 = pk2(bv.y,bv.y), b2 = pk2(bv.z,bv.z), b3 = pk2(bv.w,bv.w);
        fp[0][0]=fma2(wx01,b0,fp[0][0]); fp[1][0]=fma2(wx23,b0,fp[1][0]);
        fp[0][1]=fma2(wx01,b1,fp[0][1]); fp[1][1]=fma2(wx23,b1,fp[1][1]);
        fp[0][2]=fma2(wx01,b2,fp[0][2]); fp[1][2]=fma2(wx23,b2,fp[1][2]);
        fp[0][3]=fma2(wx01,b3,fp[0][3]); fp[1][3]=fma2(wx23,b3,fp[1][3]);
    }
    float* Fo = g_F + (size_t)blk*(PQ*NSQ);
    #pragma unroll
    for (int j=0;j<4;j++){
        float4 v;
        upk2(v.x, v.y, fp[0][j]);
        upk2(v.z, v.w, fp[1][j]);
        *(float4*)&Fo[(size_t)(n0+j)*PQ + p0] = v;   // lanes contiguous in p -> coalesced
    }
}

// ---------------- chain chunk-start states (coalesced lane partition) ----------------
__global__ __launch_bounds__(256) void k_combine(){
    const int bh  = blockIdx.x;      // 0..15
    const int tid = threadIdx.x;
    float hs[16];
    #pragma unroll
    for (int j=0;j<16;j++) hs[j]=0.f;

    // each thread owns 4 float4s at lane-contiguous positions within the 4096-elem tile
    size_t base0 = ((size_t)bh*NCH)*(PQ*NSQ) + (size_t)tid*4;
    float4 f[4];
    #pragma unroll
    for (int q=0;q<4;q++) f[q] = *(const float4*)(g_F + base0 + q*1024);
    float Pt = expf(-g_slast[bh*NCH + 0]);

    #pragma unroll 1
    for (int c=0; c<NCH; c++){
        size_t base = base0 + (size_t)c*(PQ*NSQ);
        #pragma unroll
        for (int q=0;q<4;q++)
            *(float4*)(g_Hs + base + q*1024) = make_float4(hs[4*q], hs[4*q+1], hs[4*q+2], hs[4*q+3]);
        float4 fn[4]; float Ptn = 0.f;
        if (c+1 < NCH){
            #pragma unroll
            for (int q=0;q<4;q++) fn[q] = *(const float4*)(g_F + base + (size_t)(PQ*NSQ) + q*1024);
            Ptn = expf(-g_slast[bh*NCH + c + 1]);
        }
        #pragma unroll
        for (int q=0; q<4; q++){
            hs[4*q+0] = fmaf(Pt, hs[4*q+0], f[q].x);
            hs[4*q+1] = fmaf(Pt, hs[4*q+1], f[q].y);
            hs[4*q+2] = fmaf(Pt, hs[4*q+2], f[q].z);
            hs[4*q+3] = fmaf(Pt, hs[4*q+3], f[q].w);
        }
        if (c+1 < NCH){ f[0]=fn[0]; f[1]=fn[1]; f[2]=fn[2]; f[3]=fn[3]; Pt = Ptn; }
    }
}

// ---------------- S2: full chunk output via dense matmuls (FMA2) ---------------------
// y[t][p] = sum_{s<=t} exp(S_s-S_t)*dt_s*(C_t.B_s)*x_s[p] + exp(-S_t)*(C_t.H0)[p] + D*x_t[p]
#define PADT 34
__global__ __launch_bounds__(256) void k_out(const float* __restrict__ Dparam,
                                             const float* __restrict__ Alog){
    const int blk = blockIdx.x;
    const int c   = blk & (NCH-1);
    const int bh  = blk >> 5;
    const int h   = bh & (HQ-1);
    const int b   = bh >> 3;
    const int tid = threadIdx.x;
    const int t0  = c*LC;

    __shared__ __align__(16) float sX [LC][PQ];     // [s][p]
    __shared__ __align__(16) float sBT[NSQ][PADT];  // [n][s]
    __shared__ __align__(16) float sCT[NSQ][PADT];  // [n][t]
    __shared__ __align__(16) float sM [LC][PADT];   // [s][t]
    __shared__ __align__(16) float sH [NSQ][PQ];    // [n][p]
    __shared__ float sS[LC], sDt[LC], sA[LC];

    for (int idx=tid; idx<LC*64; idx+=256){
        int s = idx >> 6, j = idx & 63;
        const float* rowp = g_xBC + (size_t)(b*LQ + t0 + s)*CONVD;
        sX[s][j]  = rowp[h*PQ + j];
        sBT[j][s] = rowp[DINQ + j];
        sCT[j][s] = rowp[DINQ + NSQ + j];
    }
    {
        const float* Hi = g_Hs + (size_t)blk*(PQ*NSQ);
        for (int idx=tid; idx<PQ*NSQ; idx+=256){
            int n = idx >> 6, p = idx & 63;
            sH[n][p] = Hi[idx];                     // already [n][p]
        }
    }
    if (tid < 32){   // fused chunk-local warp scan
        float dts = g_dt[(size_t)(b*LQ + t0 + tid)*HQ + h];
        sDt[tid] = dts;
        float v = dts * expf(Alog[h]);
        #pragma unroll
        for (int o=1; o<32; o<<=1){
            float u = __shfl_up_sync(0xffffffffu, v, o);
            if (tid >= o) v += u;
        }
        sS[tid] = v;
        sA[tid] = expf(-v);
    }
    __syncthreads();

    // ---- stage b: G = C @ B^T, then decay+mask -> M_T[s][t] ----
    {
        const int tG = tid >> 3;            // 0..31  (t index)
        const int s0 = (tid & 7) * 4;       // 0..28  (s group, 2 pairs)
        u64 g01 = 0ull, g23 = 0ull;
        #pragma unroll 8
        for (int n=0; n<NSQ; n++){
            float cv = sCT[n][tG];
            u64 cv2 = pk2(cv, cv);
            u64 b01 = *(const u64*)&sBT[n][s0];
            u64 b23 = *(const u64*)&sBT[n][s0+2];
            g01 = fma2(cv2, b01, g01);
            g23 = fma2(cv2, b23, g23);
        }
        float gx, gy, gz, gw;
        upk2(gx, gy, g01);
        upk2(gz, gw, g23);
        float St = sS[tG];
        sM[s0+0][tG] = (s0+0 <= tG) ? gx * expf(sS[s0+0] - St) * sDt[s0+0] : 0.f;
        sM[s0+1][tG] = (s0+1 <= tG) ? gy * expf(sS[s0+1] - St) * sDt[s0+1] : 0.f;
        sM[s0+2][tG] = (s0+2 <= tG) ? gz * expf(sS[s0+2] - St) * sDt[s0+2] : 0.f;
        sM[s0+3][tG] = (s0+3 <= tG) ? gw * expf(sS[s0+3] - St) * sDt[s0+3] : 0.f;
    }
    __syncthreads();

    // ---- stages c+d: Y1 = M @ X ; Ycorr = C @ H0 ; packed epilogue ----
    {
        const int tr = (tid >> 4) * 2;      // rows t = tr, tr+1
        const int pc = (tid & 15) * 4;      // 4 p = 2 pairs, lane-contiguous
        u64 y0a=0ull, y0b=0ull, y1a=0ull, y1b=0ull;
        #pragma unroll 8
        for (int s=0; s<LC; s++){
            float m0 = sM[s][tr], m1 = sM[s][tr+1];
            u64 x01 = *(const u64*)&sX[s][pc];
            u64 x23 = *(const u64*)&sX[s][pc+2];
            u64 m02 = pk2(m0,m0), m12 = pk2(m1,m1);
            y0a = fma2(m02, x01, y0a); y0b = fma2(m02, x23, y0b);
            y1a = fma2(m12, x01, y1a); y1b = fma2(m12, x23, y1b);
        }
        u64 c0a=0ull, c0b=0ull, c1a=0ull, c1b=0ull;
        #pragma unroll 8
        for (int n=0; n<NSQ; n++){
            float c0 = sCT[n][tr], c1 = sCT[n][tr+1];
            u64 h01 = *(const u64*)&sH[n][pc];
            u64 h23 = *(const u64*)&sH[n][pc+2];
            u64 c02 = pk2(c0,c0), c12 = pk2(c1,c1);
            c0a = fma2(c02, h01, c0a); c0b = fma2(c02, h23, c0b);
            c1a = fma2(c12, h01, c1a); c1b = fma2(c12, h23, c1b);
        }
        const float Dv = Dparam[h];
        const u64 Dv2 = pk2(Dv, Dv);
        {
            u64 at2 = pk2(sA[tr], sA[tr]);
            u64 x01 = *(const u64*)&sX[tr][pc];
            u64 x23 = *(const u64*)&sX[tr][pc+2];
            u64 o01 = fma2(at2, c0a, y0a); o01 = fma2(Dv2, x01, o01);
            u64 o23 = fma2(at2, c0b, y0b); o23 = fma2(Dv2, x23, o23);
            float4 o; upk2(o.x, o.y, o01); upk2(o.z, o.w, o23);
            *(float4*)&g_y[(size_t)(b*LQ + t0 + tr)*DINQ + h*PQ + pc] = o;
        }
        {
            u64 at2 = pk2(sA[tr+1], sA[tr+1]);
            u64 x01 = *(const u64*)&sX[tr+1][pc];
            u64 x23 = *(const u64*)&sX[tr+1][pc+2];
            u64 o01 = fma2(at2, c1a, y1a); o01 = fma2(Dv2, x01, o01);
            u64 o23 = fma2(at2, c1b, y1b); o23 = fma2(Dv2, x23, o23);
            float4 o; upk2(o.x, o.y, o01); upk2(o.z, o.w, o23);
            *(float4*)&g_y[(size_t)(b*LQ + t0 + tr + 1)*DINQ + h*PQ + pc] = o;
        }
    }
}

// ---------------- gate (SiLU(z)) + RMSNorm ----------------
__global__ __launch_bounds__(512) void k_gatenorm(const float* __restrict__ nw){
    int row = blockIdx.x;
    int tid = threadIdx.x;
    float y = g_y[(size_t)row*DINQ + tid];
    float z = g_zx[(size_t)row*DPROJ + tid];
    float v = y * (z / (1.f + expf(-z)));
    float ss = v*v;
    #pragma unroll
    for (int o=16;o;o>>=1) ss += __shfl_xor_sync(0xffffffffu, ss, o);
    __shared__ float red[16];
    if ((tid & 31) == 0) red[tid>>5] = ss;
    __syncthreads();
    if (tid < 32){
        float t = (tid < 16) ? red[tid] : 0.f;
        #pragma unroll
        for (int o=8;o;o>>=1) t += __shfl_xor_sync(0xffffffffu, t, o);
        if (tid == 0) red[0] = t;
    }
    __syncthreads();
    float r = rsqrtf(red[0]*(1.f/DINQ) + 1e-5f);
    g_y[(size_t)row*DINQ + tid] = v * r * nw[tid];
}

// ---------------- pooling: (mean_l + max_l) * 0.5 ----------------
__global__ void k_pool(){
    int b = blockIdx.x, d = threadIdx.x;
    const float* base = g_x + (size_t)b*LQ*DQ + d;
    float s = 0.f, m = -3.4e38f;
    #pragma unroll 8
    for (int l=0; l<LQ; l++){
        float v = base[(size_t)l*DQ];
        s += v; m = fmaxf(m, v);
    }
    g_pool[b*DQ + d] = (s*(1.f/LQ) + m)*0.5f;
}

// ---------------- classification head (single block) ----------------
__global__ __launch_bounds__(256) void k_head(const float* __restrict__ pw, const float* __restrict__ pb,
                                              const float* __restrict__ c1w, const float* __restrict__ c1b,
                                              const float* __restrict__ c2w, const float* __restrict__ c2b,
                                              float* __restrict__ out){
    __shared__ __align__(16) float sp[BQ*DQ];
    __shared__ __align__(16) float h1[BQ*DQ];
    __shared__ __align__(16) float h2[BQ*128];
    int tid = threadIdx.x;
    for (int i=tid; i<BQ*DQ; i+=256) sp[i] = g_pool[i];
    __syncthreads();
    for (int i=tid; i<BQ*DQ; i+=256){
        int b = i >> 8, o = i & 255;
        const float4* xr = (const float4*)(sp + b*DQ);
        const float4* wr = (const float4*)(pw + (size_t)o*DQ);
        float a = pb[o];
        #pragma unroll 8
        for (int k=0; k<DQ/4; k++){
            float4 xv = xr[k], wv = wr[k];
            a = fmaf(xv.x,wv.x,a); a = fmaf(xv.y,wv.y,a);
            a = fmaf(xv.z,wv.z,a); a = fmaf(xv.w,wv.w,a);
        }
        h1[i] = geluf(a);
    }
    __syncthreads();
    {
        int b = tid >> 7, o = tid & 127;
        const float4* xr = (const float4*)(h1 + b*DQ);
        const float4* wr = (const float4*)(c1w + (size_t)o*DQ);
        float a = c1b[o];
        #pragma unroll 8
        for (int k=0; k<DQ/4; k++){
            float4 xv = xr[k], wv = wr[k];
            a = fmaf(xv.x,wv.x,a); a = fmaf(xv.y,wv.y,a);
            a = fmaf(xv.z,wv.z,a); a = fmaf(xv.w,wv.w,a);
        }
        h2[tid] = geluf(a);
    }
    __syncthreads();
    if (tid < 4){
        int b = tid >> 1, o = tid & 1;
        const float* xr = h2 + b*128;
        const float* wr = c2w + o*128;
        float a = c2b[o];
        #pragma unroll 8
        for (int k=0; k<128; k++) a = fmaf(xr[k], wr[k], a);
        out[b*2 + o] = a;
    }
}

// ---------------- launcher ----------------
extern "C" void kernel_launch(void* const* d_in, const int* in_sizes, int n_in,
                              void* d_out, int out_size){
    (void)in_sizes; (void)n_in; (void)out_size;
    const int*   ids  = (const int*)  d_in[0];
    const float* emb  = (const float*)d_in[1];
    const float* pos  = (const float*)d_in[2];
    const float* Win  = (const float*)d_in[3];
    const float* cw   = (const float*)d_in[4];
    const float* cb   = (const float*)d_in[5];
    const float* dtb  = (const float*)d_in[6];
    const float* Alog = (const float*)d_in[7];
    const float* Dpar = (const float*)d_in[8];
    const float* nw   = (const float*)d_in[9];
    const float* Wout = (const float*)d_in[10];
    const float* pw   = (const float*)d_in[11];
    const float* pb   = (const float*)d_in[12];
    const float* c1w  = (const float*)d_in[13];
    const float* c1b  = (const float*)d_in[14];
    const float* c2w  = (const float*)d_in[15];
    const float* c2b  = (const float*)d_in[16];
    float* out = (float*)d_out;

    k_embed<<<BQ*LQ, DQ>>>(ids, emb, pos);
    for (int i=0; i<NLQ; i++){
        k_gemm_in <<<dim3((DPROJ+63)/64, (BQ*LQ)/128), 128>>>(Win + (size_t)i*DPROJ*DQ);
        k_convdt  <<<BQ*LQ, CONVD>>>(cw + (size_t)i*CONVD*4, cb + (size_t)i*CONVD,
                                     dtb + (size_t)i*HQ);
        k_state   <<<BQ*HQ*NCH, 256>>>(Alog + (size_t)i*HQ);
        k_combine <<<BQ*HQ, 256>>>();
        k_out     <<<BQ*HQ*NCH, 256>>>(Dpar + (size_t)i*HQ, Alog + (size_t)i*HQ);
        k_gatenorm<<<BQ*LQ, DINQ>>>(nw + (size_t)i*DINQ);
        k_gemm_out<<<dim3(DQ/64, (BQ*LQ)/64), 128>>>(Wout + (size_t)i*DQ*DINQ);
    }
    k_pool<<<BQ, DQ>>>();
    k_head<<<1, 256>>>(pw, pb, c1w, c1b, c2w, c2b, out);
}

// round 10
// speedup vs baseline: 1.3263x; 1.3263x over previous
#include <cuda_runtime.h>
#include <math.h>

// ---------------- problem constants ----------------
#define BQ     2
#define LQ     1024
#define DQ     256
#define NLQ    4
#define DINQ   512
#define HQ     8
#define PQ     64
#define NSQ    64
#define CONVD  640           // DIN + 2*NSTATE
#define DPROJ  1160          // 2*DIN + 2*NSTATE + H
#define NCH    32            // chunks
#define LC     32            // chunk length (LQ / NCH)

typedef unsigned long long u64;

// packed fp32x2 helpers (sm_100+): one instr = two fp32 FMAs, exact fp32 math
__device__ __forceinline__ u64 pk2(float lo, float hi){
    u64 r; asm("mov.b64 %0, {%1, %2};" : "=l"(r) : "f"(lo), "f"(hi)); return r;
}
__device__ __forceinline__ void upk2(float& lo, float& hi, u64 v){
    asm("mov.b64 {%0, %1}, %2;" : "=f"(lo), "=f"(hi) : "l"(v));
}
__device__ __forceinline__ u64 fma2(u64 a, u64 b, u64 c){
    u64 d; asm("fma.rn.f32x2 %0, %1, %2, %3;" : "=l"(d) : "l"(a), "l"(b), "l"(c)); return d;
}
__device__ __forceinline__ u64 mul2(u64 a, u64 b){
    u64 d; asm("mul.rn.f32x2 %0, %1, %2;" : "=l"(d) : "l"(a), "l"(b)); return d;
}

// ---------------- scratch (device globals; no allocation) ----------------
static __device__ float g_x  [BQ*LQ*DQ];
static __device__ float g_zx [BQ*LQ*DPROJ];
static __device__ float g_xBC[BQ*LQ*CONVD];
static __device__ float g_dt [BQ*LQ*HQ];
static __device__ float g_slast[BQ*HQ*NCH];              // per-chunk S_last
static __device__ float g_y  [BQ*LQ*DINQ];
static __device__ float g_F  [BQ*HQ*NCH*PQ*NSQ];         // chunk-final local state [blk][n][p]
static __device__ float g_Hs [BQ*HQ*NCH*PQ*NSQ];         // chunk-START state H0   [blk][n][p]
static __device__ float g_pool[BQ*DQ];

__device__ __forceinline__ float geluf(float x){
    return 0.5f * x * (1.0f + erff(x * 0.7071067811865476f));
}

// ---------------- embedding ----------------
__global__ void k_embed(const int* __restrict__ ids, const float* __restrict__ emb,
                        const float* __restrict__ pos){
    int row = blockIdx.x;            // b*LQ + l
    int l   = row & (LQ-1);
    int d   = threadIdx.x;
    g_x[(size_t)row*DQ + d] = emb[(size_t)ids[row]*DQ + d] + pos[(size_t)l*DQ + d];
}

// ================= GEMM 128x64 (FMA2, prefetch-pipelined): C[m,n]=sum_k A[m,k]B[n,k] ==
template<int M, int N, int K, bool ACC>
__device__ __forceinline__ void gemm128(const float* __restrict__ A,
                                        const float* __restrict__ Bw,
                                        float* __restrict__ Cc){
    constexpr int BM=128, BN=64, BK=16;
    __shared__ __align__(16) float As[2][BK][BM];
    __shared__ __align__(16) float Bs[2][BK][BN];
    const int tid = threadIdx.x;
    const int bm  = blockIdx.y * BM;
    const int bn  = blockIdx.x * BN;
    const int alr = tid & 127;
    const int alc = (tid >> 7) * 8;
    const int blr = tid & 63;
    const int blc = (tid >> 6) * 4;
    const int tr  = (tid >> 4) * 8;    // m-offset (8 rows = 4 pairs)
    const int tc  = (tid & 15) * 4;    // n-offset (4 cols)

    const bool bvalid = (N % BN == 0) || (bn + blr < N);
    const float* Aptr = A  + (size_t)(bm + alr)*K + alc;
    const float* Bptr = Bw + (size_t)(bn + blr)*K + blc;

    u64 accp[4][4];                    // [m-pair][n]
    #pragma unroll
    for (int m=0;m<4;m++)
        #pragma unroll
        for (int n=0;n<4;n++) accp[m][n]=0ull;

    float4 ra0, ra1, rb0;
    auto ldg = [&](int k0){
        ra0 = *(const float4*)(Aptr + k0);
        ra1 = *(const float4*)(Aptr + k0 + 4);
        rb0 = make_float4(0.f,0.f,0.f,0.f);
        if (bvalid) rb0 = *(const float4*)(Bptr + k0);
    };
    auto sts = [&](int buf){
        As[buf][alc+0][alr]=ra0.x; As[buf][alc+1][alr]=ra0.y;
        As[buf][alc+2][alr]=ra0.z; As[buf][alc+3][alr]=ra0.w;
        As[buf][alc+4][alr]=ra1.x; As[buf][alc+5][alr]=ra1.y;
        As[buf][alc+6][alr]=ra1.z; As[buf][alc+7][alr]=ra1.w;
        Bs[buf][blc+0][blr]=rb0.x; Bs[buf][blc+1][blr]=rb0.y;
        Bs[buf][blc+2][blr]=rb0.z; Bs[buf][blc+3][blr]=rb0.w;
    };

    ldg(0); sts(0);
    __syncthreads();
    constexpr int NK = K/BK;
    #pragma unroll 1
    for (int kt=0; kt<NK; kt++){
        if (kt+1 < NK) ldg((kt+1)*BK);
        const int cur = kt & 1;
        #pragma unroll
        for (int kk=0; kk<BK; kk++){
            u64 a0 = *(const u64*)&As[cur][kk][tr];
            u64 a1 = *(const u64*)&As[cur][kk][tr+2];
            u64 a2 = *(const u64*)&As[cur][kk][tr+4];
            u64 a3 = *(const u64*)&As[cur][kk][tr+6];
            float4 b = *(const float4*)&Bs[cur][kk][tc];
            u64 b0 = pk2(b.x,b.x), b1 = pk2(b.y,b.y), b2 = pk2(b.z,b.z), b3 = pk2(b.w,b.w);
            accp[0][0]=fma2(a0,b0,accp[0][0]); accp[0][1]=fma2(a0,b1,accp[0][1]);
            accp[0][2]=fma2(a0,b2,accp[0][2]); accp[0][3]=fma2(a0,b3,accp[0][3]);
            accp[1][0]=fma2(a1,b0,accp[1][0]); accp[1][1]=fma2(a1,b1,accp[1][1]);
            accp[1][2]=fma2(a1,b2,accp[1][2]); accp[1][3]=fma2(a1,b3,accp[1][3]);
            accp[2][0]=fma2(a2,b0,accp[2][0]); accp[2][1]=fma2(a2,b1,accp[2][1]);
            accp[2][2]=fma2(a2,b2,accp[2][2]); accp[2][3]=fma2(a2,b3,accp[2][3]);
            accp[3][0]=fma2(a3,b0,accp[3][0]); accp[3][1]=fma2(a3,b1,accp[3][1]);
            accp[3][2]=fma2(a3,b2,accp[3][2]); accp[3][3]=fma2(a3,b3,accp[3][3]);
        }
        if (kt+1 < NK) sts((kt+1) & 1);
        __syncthreads();
    }
    const int col0 = bn + tc;
    const bool cvalid = (N % BN == 0) || (col0 < N);
    #pragma unroll
    for (int mp=0; mp<4; mp++){
        float4 lo, hi;
        upk2(lo.x, hi.x, accp[mp][0]);
        upk2(lo.y, hi.y, accp[mp][1]);
        upk2(lo.z, hi.z, accp[mp][2]);
        upk2(lo.w, hi.w, accp[mp][3]);
        if (cvalid){
            size_t i0 = (size_t)(bm + tr + 2*mp)*N + col0;
            size_t i1 = i0 + N;
            if (ACC){
                float4 c0 = *(float4*)&Cc[i0];
                float4 c1 = *(float4*)&Cc[i1];
                c0.x+=lo.x; c0.y+=lo.y; c0.z+=lo.z; c0.w+=lo.w;
                c1.x+=hi.x; c1.y+=hi.y; c1.z+=hi.z; c1.w+=hi.w;
                *(float4*)&Cc[i0] = c0;
                *(float4*)&Cc[i1] = c1;
            } else {
                *(float4*)&Cc[i0] = lo;
                *(float4*)&Cc[i1] = hi;
            }
        }
    }
}

// ================= GEMM 64x64 (FMA2, prefetch-pipelined) =================
template<int M, int N, int K, bool ACC>
__device__ __forceinline__ void gemm64(const float* __restrict__ A,
                                       const float* __restrict__ Bw,
                                       float* __restrict__ Cc){
    constexpr int BM=64, BN=64, BK=16;
    __shared__ __align__(16) float As[2][BK][BM];
    __shared__ __align__(16) float Bs[2][BK][BN];
    const int tid = threadIdx.x;
    const int bm  = blockIdx.y * BM;
    const int bn  = blockIdx.x * BN;
    const int lr  = tid & 63;
    const int lc  = (tid >> 6) * 4;
    const int tr  = (tid >> 4) * 4;    // 4 rows = 2 pairs
    const int tc  = (tid & 15) * 4;

    const bool bvalid = (N % BN == 0) || (bn + lr < N);
    const float* Aptr = A  + (size_t)(bm + lr)*K + lc;
    const float* Bptr = Bw + (size_t)(bn + lr)*K + lc;

    u64 accp[2][4];
    #pragma unroll
    for (int m=0;m<2;m++)
        #pragma unroll
        for (int n=0;n<4;n++) accp[m][n]=0ull;

    float4 ra, rb;
    auto ldg = [&](int k0){
        ra = *(const float4*)(Aptr + k0);
        rb = make_float4(0.f,0.f,0.f,0.f);
        if (bvalid) rb = *(const float4*)(Bptr + k0);
    };
    auto sts = [&](int buf){
        As[buf][lc+0][lr]=ra.x; As[buf][lc+1][lr]=ra.y;
        As[buf][lc+2][lr]=ra.z; As[buf][lc+3][lr]=ra.w;
        Bs[buf][lc+0][lr]=rb.x; Bs[buf][lc+1][lr]=rb.y;
        Bs[buf][lc+2][lr]=rb.z; Bs[buf][lc+3][lr]=rb.w;
    };

    ldg(0); sts(0);
    __syncthreads();
    constexpr int NK = K/BK;
    #pragma unroll 1
    for (int kt=0; kt<NK; kt++){
        if (kt+1 < NK) ldg((kt+1)*BK);
        const int cur = kt & 1;
        #pragma unroll
        for (int kk=0; kk<BK; kk++){
            u64 a0 = *(const u64*)&As[cur][kk][tr];
            u64 a1 = *(const u64*)&As[cur][kk][tr+2];
            float4 b = *(const float4*)&Bs[cur][kk][tc];
            u64 b0 = pk2(b.x,b.x), b1 = pk2(b.y,b.y), b2 = pk2(b.z,b.z), b3 = pk2(b.w,b.w);
            accp[0][0]=fma2(a0,b0,accp[0][0]); accp[0][1]=fma2(a0,b1,accp[0][1]);
            accp[0][2]=fma2(a0,b2,accp[0][2]); accp[0][3]=fma2(a0,b3,accp[0][3]);
            accp[1][0]=fma2(a1,b0,accp[1][0]); accp[1][1]=fma2(a1,b1,accp[1][1]);
            accp[1][2]=fma2(a1,b2,accp[1][2]); accp[1][3]=fma2(a1,b3,accp[1][3]);
        }
        if (kt+1 < NK) sts((kt+1) & 1);
        __syncthreads();
    }
    const int col0 = bn + tc;
    const bool cvalid = (N % BN == 0) || (col0 < N);
    #pragma unroll
    for (int mp=0; mp<2; mp++){
        float4 lo, hi;
        upk2(lo.x, hi.x, accp[mp][0]);
        upk2(lo.y, hi.y, accp[mp][1]);
        upk2(lo.z, hi.z, accp[mp][2]);
        upk2(lo.w, hi.w, accp[mp][3]);
        if (cvalid){
            size_t i0 = (size_t)(bm + tr + 2*mp)*N + col0;
            size_t i1 = i0 + N;
            if (ACC){
                float4 c0 = *(float4*)&Cc[i0];
                float4 c1 = *(float4*)&Cc[i1];
                c0.x+=lo.x; c0.y+=lo.y; c0.z+=lo.z; c0.w+=lo.w;
                c1.x+=hi.x; c1.y+=hi.y; c1.z+=hi.z; c1.w+=hi.w;
                *(float4*)&Cc[i0] = c0;
                *(float4*)&Cc[i1] = c1;
            } else {
                *(float4*)&Cc[i0] = lo;
                *(float4*)&Cc[i1] = hi;
            }
        }
    }
}

__global__ __launch_bounds__(256) void k_gemm_in(const float* __restrict__ W){
    gemm128<BQ*LQ, DPROJ, DQ, false>(g_x, W, g_zx);
}
__global__ __launch_bounds__(256) void k_gemm_out(const float* __restrict__ W){
    gemm64<BQ*LQ, DQ, DINQ, true>(g_y, W, g_x);
}

// ---------------- depthwise causal conv + SiLU, and dt ----------------
__global__ void k_convdt(const float* __restrict__ cw, const float* __restrict__ cb,
                         const float* __restrict__ dtb){
    int row = blockIdx.x;            // b*LQ + l
    int l   = row & (LQ-1);
    int ci  = threadIdx.x;           // 0..639
    float4 w = *(const float4*)(cw + ci*4);   // conv_w[ci][0..3]
    const float* src = g_zx + (size_t)row*DPROJ + DINQ + ci;
    float acc = cb[ci];
    acc = fmaf(w.w, src[0], acc);
    if (l >= 1) acc = fmaf(w.z, src[-DPROJ],   acc);
    if (l >= 2) acc = fmaf(w.y, src[-2*DPROJ], acc);
    if (l >= 3) acc = fmaf(w.x, src[-3*DPROJ], acc);
    g_xBC[(size_t)row*CONVD + ci] = acc / (1.f + expf(-acc));   // SiLU
    if (ci < HQ){
        float raw = g_zx[(size_t)row*DPROJ + (DINQ + CONVD) + ci] + dtb[ci];
        float dt  = (raw > 20.f) ? raw : log1pf(expf(raw));     // softplus
        g_dt[(size_t)row*HQ + ci] = dt;
    }
}

// ---------------- S1: per-chunk local final state F[n][p] (+ fused warp-scan) ---------
// p contiguous across lanes -> coalesced float4 stores of g_F
__global__ __launch_bounds__(256) void k_state(const float* __restrict__ Alog){
    const int blk = blockIdx.x;
    const int c   = blk & (NCH-1);
    const int bh  = blk >> 5;
    const int h   = bh & (HQ-1);
    const int b   = bh >> 3;
    const int tid = threadIdx.x;
    const int t0  = c*LC;

    __shared__ __align__(16) float sX[LC][PQ];
    __shared__ __align__(16) float sB[LC][NSQ];
    __shared__ float sW[LC];

    for (int idx=tid; idx<LC*128; idx+=256){
        int s = idx >> 7, j = idx & 127;
        const float* rowp = g_xBC + (size_t)(b*LQ + t0 + s)*CONVD;
        if (j < 64) sX[s][j]    = rowp[h*PQ + j];
        else        sB[s][j-64] = rowp[DINQ + (j-64)];
    }
    if (tid < 32){   // chunk-local inclusive cumsum of dt*|A| via warp scan
        float dts  = g_dt[(size_t)(b*LQ + t0 + tid)*HQ + h];
        float v = dts * expf(Alog[h]);
        #pragma unroll
        for (int o=1; o<32; o<<=1){
            float u = __shfl_up_sync(0xffffffffu, v, o);
            if (tid >= o) v += u;
        }
        float Sl = __shfl_sync(0xffffffffu, v, 31);
        sW[tid] = expf(v - Sl) * dts;
        if (tid == 31) g_slast[blk] = v;
    }
    __syncthreads();

    const int p0 = (tid & 15) * 4;     // p contiguous across lanes
    const int n0 = (tid >> 4) * 4;     // n broadcast within half-warp
    u64 fp[2][4];                       // [p-pair][n]
    #pragma unroll
    for (int i=0;i<2;i++)
        #pragma unroll
        for (int j=0;j<4;j++) fp[i][j]=0ull;

    #pragma unroll 4
    for (int s=0; s<LC; s++){
        u64 x01 = *(const u64*)&sX[s][p0];
        u64 x23 = *(const u64*)&sX[s][p0+2];
        float4 bv = *(const float4*)&sB[s][n0];
        float w = sW[s];
        u64 w2 = pk2(w,w);
        u64 wx01 = mul2(x01, w2);
        u64 wx23 = mul2(x23, w2);
        u64 b0 = pk2(bv.x,bv.x), b1 = pk2(bv.y,bv.y), b2 = pk2(bv.z,bv.z), b3 = pk2(bv.w,bv.w);
        fp[0][0]=fma2(wx01,b0,fp[0][0]); fp[1][0]=fma2(wx23,b0,fp[1][0]);
        fp[0][1]=fma2(wx01,b1,fp[0][1]); fp[1][1]=fma2(wx23,b1,fp[1][1]);
        fp[0][2]=fma2(wx01,b2,fp[0][2]); fp[1][2]=fma2(wx23,b2,fp[1][2]);
        fp[0][3]=fma2(wx01,b3,fp[0][3]); fp[1][3]=fma2(wx23,b3,fp[1][3]);
    }
    float* Fo = g_F + (size_t)blk*(PQ*NSQ);
    #pragma unroll
    for (int j=0;j<4;j++){
        float4 v;
        upk2(v.x, v.y, fp[0][j]);
        upk2(v.z, v.w, fp[1][j]);
        *(float4*)&Fo[(size_t)(n0+j)*PQ + p0] = v;   // lanes contiguous in p -> coalesced
    }
}

// ---------------- chain chunk-start states: one thread per element, MLP=32 -----------
// H0[c][e] scan: hs=0; for c: H0[c]=hs; hs = exp(-slast[c])*hs + F[c][e]
__global__ __launch_bounds__(256) void k_combine(){
    const int blk = blockIdx.x;              // 0..255 (16 per bh)
    const int bh  = blk >> 4;
    const int e   = (blk & 15)*256 + threadIdx.x;   // element 0..4095
    __shared__ float sP[NCH];
    if (threadIdx.x < NCH) sP[threadIdx.x] = expf(-g_slast[bh*NCH + threadIdx.x]);
    __syncthreads();
    const float* Fp = g_F  + (size_t)bh*NCH*(PQ*NSQ) + e;
    float*       Hp = g_Hs + (size_t)bh*NCH*(PQ*NSQ) + e;
    float f[NCH];
    #pragma unroll
    for (int c=0; c<NCH; c++) f[c] = Fp[(size_t)c*(PQ*NSQ)];   // 32 independent coalesced LDGs
    float hs = 0.f;
    #pragma unroll
    for (int c=0; c<NCH; c++){
        Hp[(size_t)c*(PQ*NSQ)] = hs;
        hs = fmaf(sP[c], hs, f[c]);
    }
}

// ---------------- S2: full chunk output via dense matmuls (FMA2) ---------------------
// y[t][p] = sum_{s<=t} exp(S_s-S_t)*dt_s*(C_t.B_s)*x_s[p] + exp(-S_t)*(C_t.H0)[p] + D*x_t[p]
#define PADT 36
__global__ __launch_bounds__(256) void k_out(const float* __restrict__ Dparam,
                                             const float* __restrict__ Alog){
    const int blk = blockIdx.x;
    const int c   = blk & (NCH-1);
    const int bh  = blk >> 5;
    const int h   = bh & (HQ-1);
    const int b   = bh >> 3;
    const int tid = threadIdx.x;
    const int t0  = c*LC;

    __shared__ __align__(16) float sX [LC][PQ];     // [s][p]
    __shared__ __align__(16) float sBT[NSQ][PADT];  // [n][s]
    __shared__ __align__(16) float sCT[NSQ][PADT];  // [n][t]
    __shared__ __align__(16) float sM [LC][PADT];   // [s][t]
    __shared__ __align__(16) float sH [NSQ][PQ];    // [n][p]
    __shared__ float sS[LC], sDt[LC], sA[LC];

    for (int idx=tid; idx<LC*64; idx+=256){
        int s = idx >> 6, j = idx & 63;
        const float* rowp = g_xBC + (size_t)(b*LQ + t0 + s)*CONVD;
        sX[s][j]  = rowp[h*PQ + j];
        sBT[j][s] = rowp[DINQ + j];
        sCT[j][s] = rowp[DINQ + NSQ + j];
    }
    {
        const float* Hi = g_Hs + (size_t)blk*(PQ*NSQ);
        for (int idx=tid; idx<PQ*NSQ; idx+=256){
            int n = idx >> 6, p = idx & 63;
            sH[n][p] = Hi[idx];                     // already [n][p]
        }
    }
    if (tid < 32){   // fused chunk-local warp scan
        float dts = g_dt[(size_t)(b*LQ + t0 + tid)*HQ + h];
        sDt[tid] = dts;
        float v = dts * expf(Alog[h]);
        #pragma unroll
        for (int o=1; o<32; o<<=1){
            float u = __shfl_up_sync(0xffffffffu, v, o);
            if (tid >= o) v += u;
        }
        sS[tid] = v;
        sA[tid] = expf(-v);
    }
    __syncthreads();

    // ---- stage b: G = C @ B^T, then decay+mask -> M_T[s][t] ----
    {
        const int tG = tid >> 3;            // 0..31  (t index)
        const int s0 = (tid & 7) * 4;       // 0..28  (s group, 2 pairs)
        u64 g01 = 0ull, g23 = 0ull;
        #pragma unroll 8
        for (int n=0; n<NSQ; n++){
            float cv = sCT[n][tG];
            u64 cv2 = pk2(cv, cv);
            u64 b01 = *(const u64*)&sBT[n][s0];
            u64 b23 = *(const u64*)&sBT[n][s0+2];
            g01 = fma2(cv2, b01, g01);
            g23 = fma2(cv2, b23, g23);
        }
        float gx, gy, gz, gw;
        upk2(gx, gy, g01);
        upk2(gz, gw, g23);
        float St = sS[tG];
        sM[s0+0][tG] = (s0+0 <= tG) ? gx * expf(sS[s0+0] - St) * sDt[s0+0] : 0.f;
        sM[s0+1][tG] = (s0+1 <= tG) ? gy * expf(sS[s0+1] - St) * sDt[s0+1] : 0.f;
        sM[s0+2][tG] = (s0+2 <= tG) ? gz * expf(sS[s0+2] - St) * sDt[s0+2] : 0.f;
        sM[s0+3][tG] = (s0+3 <= tG) ? gw * expf(sS[s0+3] - St) * sDt[s0+3] : 0.f;
    }
    __syncthreads();

    // ---- stages c+d: Y1 = M @ X ; Ycorr = C @ H0 ; packed epilogue ----
    {
        const int tr = (tid >> 4) * 2;      // rows t = tr, tr+1
        const int pc = (tid & 15) * 4;      // 4 p = 2 pairs
        u64 y0a=0ull, y0b=0ull, y1a=0ull, y1b=0ull;
        #pragma unroll 8
        for (int s=0; s<LC; s++){
            float m0 = sM[s][tr], m1 = sM[s][tr+1];
            u64 x01 = *(const u64*)&sX[s][pc];
            u64 x23 = *(const u64*)&sX[s][pc+2];
            u64 m02 = pk2(m0,m0), m12 = pk2(m1,m1);
            y0a = fma2(m02, x01, y0a); y0b = fma2(m02, x23, y0b);
            y1a = fma2(m12, x01, y1a); y1b = fma2(m12, x23, y1b);
        }
        u64 c0a=0ull, c0b=0ull, c1a=0ull, c1b=0ull;
        #pragma unroll 8
        for (int n=0; n<NSQ; n++){
            float c0 = sCT[n][tr], c1 = sCT[n][tr+1];
            u64 h01 = *(const u64*)&sH[n][pc];
            u64 h23 = *(const u64*)&sH[n][pc+2];
            u64 c02 = pk2(c0,c0), c12 = pk2(c1,c1);
            c0a = fma2(c02, h01, c0a); c0b = fma2(c02, h23, c0b);
            c1a = fma2(c12, h01, c1a); c1b = fma2(c12, h23, c1b);
        }
        const float Dv = Dparam[h];
        const u64 Dv2 = pk2(Dv, Dv);
        {
            u64 at2 = pk2(sA[tr], sA[tr]);
            u64 x01 = *(const u64*)&sX[tr][pc];
            u64 x23 = *(const u64*)&sX[tr][pc+2];
            u64 o01 = fma2(at2, c0a, y0a); o01 = fma2(Dv2, x01, o01);
            u64 o23 = fma2(at2, c0b, y0b); o23 = fma2(Dv2, x23, o23);
            float4 o; upk2(o.x, o.y, o01); upk2(o.z, o.w, o23);
            *(float4*)&g_y[(size_t)(b*LQ + t0 + tr)*DINQ + h*PQ + pc] = o;
        }
        {
            u64 at2 = pk2(sA[tr+1], sA[tr+1]);
            u64 x01 = *(const u64*)&sX[tr+1][pc];
            u64 x23 = *(const u64*)&sX[tr+1][pc+2];
            u64 o01 = fma2(at2, c1a, y1a); o01 = fma2(Dv2, x01, o01);
            u64 o23 = fma2(at2, c1b, y1b); o23 = fma2(Dv2, x23, o23);
            float4 o; upk2(o.x, o.y, o01); upk2(o.z, o.w, o23);
            *(float4*)&g_y[(size_t)(b*LQ + t0 + tr + 1)*DINQ + h*PQ + pc] = o;
        }
    }
}

// ---------------- gate (SiLU(z)) + RMSNorm ----------------
__global__ __launch_bounds__(512) void k_gatenorm(const float* __restrict__ nw){
    int row = blockIdx.x;
    int tid = threadIdx.x;
    float y = g_y[(size_t)row*DINQ + tid];
    float z = g_zx[(size_t)row*DPROJ + tid];
    float v = y * (z / (1.f + expf(-z)));
    float ss = v*v;
    #pragma unroll
    for (int o=16;o;o>>=1) ss += __shfl_xor_sync(0xffffffffu, ss, o);
    __shared__ float red[16];
    if ((tid & 31) == 0) red[tid>>5] = ss;
    __syncthreads();
    if (tid < 32){
        float t = (tid < 16) ? red[tid] : 0.f;
        #pragma unroll
        for (int o=8;o;o>>=1) t += __shfl_xor_sync(0xffffffffu, t, o);
        if (tid == 0) red[0] = t;
    }
    __syncthreads();
    float r = rsqrtf(red[0]*(1.f/DINQ) + 1e-5f);
    g_y[(size_t)row*DINQ + tid] = v * r * nw[tid];
}

// ---------------- pooling: (mean_l + max_l) * 0.5 ----------------
__global__ void k_pool(){
    int b = blockIdx.x, d = threadIdx.x;
    const float* base = g_x + (size_t)b*LQ*DQ + d;
    float s = 0.f, m = -3.4e38f;
    #pragma unroll 8
    for (int l=0; l<LQ; l++){
        float v = base[(size_t)l*DQ];
        s += v; m = fmaxf(m, v);
    }
    g_pool[b*DQ + d] = (s*(1.f/LQ) + m)*0.5f;
}

// ---------------- classification head (single block) ----------------
__global__ __launch_bounds__(256) void k_head(const float* __restrict__ pw, const float* __restrict__ pb,
                                              const float* __restrict__ c1w, const float* __restrict__ c1b,
                                              const float* __restrict__ c2w, const float* __restrict__ c2b,
                                              float* __restrict__ out){
    __shared__ __align__(16) float sp[BQ*DQ];
    __shared__ __align__(16) float h1[BQ*DQ];
    __shared__ __align__(16) float h2[BQ*128];
    int tid = threadIdx.x;
    for (int i=tid; i<BQ*DQ; i+=256) sp[i] = g_pool[i];
    __syncthreads();
    for (int i=tid; i<BQ*DQ; i+=256){
        int b = i >> 8, o = i & 255;
        const float4* xr = (const float4*)(sp + b*DQ);
        const float4* wr = (const float4*)(pw + (size_t)o*DQ);
        float a = pb[o];
        #pragma unroll 8
        for (int k=0; k<DQ/4; k++){
            float4 xv = xr[k], wv = wr[k];
            a = fmaf(xv.x,wv.x,a); a = fmaf(xv.y,wv.y,a);
            a = fmaf(xv.z,wv.z,a); a = fmaf(xv.w,wv.w,a);
        }
        h1[i] = geluf(a);
    }
    __syncthreads();
    {
        int b = tid >> 7, o = tid & 127;
        const float4* xr = (const float4*)(h1 + b*DQ);
        const float4* wr = (const float4*)(c1w + (size_t)o*DQ);
        float a = c1b[o];
        #pragma unroll 8
        for (int k=0; k<DQ/4; k++){
            float4 xv = xr[k], wv = wr[k];
            a = fmaf(xv.x,wv.x,a); a = fmaf(xv.y,wv.y,a);
            a = fmaf(xv.z,wv.z,a); a = fmaf(xv.w,wv.w,a);
        }
        h2[tid] = geluf(a);
    }
    __syncthreads();
    if (tid < 4){
        int b = tid >> 1, o = tid & 1;
        const float* xr = h2 + b*128;
        const float* wr = c2w + o*128;
        float a = c2b[o];
        #pragma unroll 8
        for (int k=0; k<128; k++) a = fmaf(xr[k], wr[k], a);
        out[b*2 + o] = a;
    }
}

// ---------------- launcher ----------------
extern "C" void kernel_launch(void* const* d_in, const int* in_sizes, int n_in,
                              void* d_out, int out_size){
    (void)in_sizes; (void)n_in; (void)out_size;
    const int*   ids  = (const int*)  d_in[0];
    const float* emb  = (const float*)d_in[1];
    const float* pos  = (const float*)d_in[2];
    const float* Win  = (const float*)d_in[3];
    const float* cw   = (const float*)d_in[4];
    const float* cb   = (const float*)d_in[5];
    const float* dtb  = (const float*)d_in[6];
    const float* Alog = (const float*)d_in[7];
    const float* Dpar = (const float*)d_in[8];
    const float* nw   = (const float*)d_in[9];
    const float* Wout = (const float*)d_in[10];
    const float* pw   = (const float*)d_in[11];
    const float* pb   = (const float*)d_in[12];
    const float* c1w  = (const float*)d_in[13];
    const float* c1b  = (const float*)d_in[14];
    const float* c2w  = (const float*)d_in[15];
    const float* c2b  = (const float*)d_in[16];
    float* out = (float*)d_out;

    k_embed<<<BQ*LQ, DQ>>>(ids, emb, pos);
    for (int i=0; i<NLQ; i++){
        k_gemm_in <<<dim3((DPROJ+63)/64, (BQ*LQ)/128), 256>>>(Win + (size_t)i*DPROJ*DQ);
        k_convdt  <<<BQ*LQ, CONVD>>>(cw + (size_t)i*CONVD*4, cb + (size_t)i*CONVD,
                                     dtb + (size_t)i*HQ);
        k_state   <<<BQ*HQ*NCH, 256>>>(Alog + (size_t)i*HQ);
        k_combine <<<BQ*HQ*16, 256>>>();
        k_out     <<<BQ*HQ*NCH, 256>>>(Dpar + (size_t)i*HQ, Alog + (size_t)i*HQ);
        k_gatenorm<<<BQ*LQ, DINQ>>>(nw + (size_t)i*DINQ);
        k_gemm_out<<<dim3(DQ/64, (BQ*LQ)/64), 256>>>(Wout + (size_t)i*DQ*DINQ);
    }
    k_pool<<<BQ, DQ>>>();
    k_head<<<1, 256>>>(pw, pb, c1w, c1b, c2w, c2b, out);
}

// round 12
// speedup vs baseline: 1.3946x; 1.0515x over previous
#include <cuda_runtime.h>
#include <math.h>

// ---------------- problem constants ----------------
#define BQ     2
#define LQ     1024
#define DQ     256
#define NLQ    4
#define DINQ   512
#define HQ     8
#define PQ     64
#define NSQ    64
#define CONVD  640           // DIN + 2*NSTATE
#define DPROJ  1160          // 2*DIN + 2*NSTATE + H
#define NCH    32            // chunks
#define LC     32            // chunk length (LQ / NCH)

typedef unsigned long long u64;

// packed fp32x2 helpers (sm_100+): one instr = two fp32 FMAs, exact fp32 math
__device__ __forceinline__ u64 pk2(float lo, float hi){
    u64 r; asm("mov.b64 %0, {%1, %2};" : "=l"(r) : "f"(lo), "f"(hi)); return r;
}
__device__ __forceinline__ void upk2(float& lo, float& hi, u64 v){
    asm("mov.b64 {%0, %1}, %2;" : "=f"(lo), "=f"(hi) : "l"(v));
}
__device__ __forceinline__ u64 fma2(u64 a, u64 b, u64 c){
    u64 d; asm("fma.rn.f32x2 %0, %1, %2, %3;" : "=l"(d) : "l"(a), "l"(b), "l"(c)); return d;
}
__device__ __forceinline__ u64 mul2(u64 a, u64 b){
    u64 d; asm("mul.rn.f32x2 %0, %1, %2;" : "=l"(d) : "l"(a), "l"(b)); return d;
}

// ---------------- scratch (device globals; no allocation) ----------------
static __device__ float g_x  [BQ*LQ*DQ];
static __device__ float g_zx [BQ*LQ*DPROJ];
static __device__ float g_xBC[BQ*LQ*CONVD];
static __device__ float g_dt [BQ*LQ*HQ];
static __device__ float g_slast[BQ*HQ*NCH];              // per-chunk S_last
static __device__ float g_y  [BQ*LQ*DINQ];
static __device__ float g_F  [BQ*HQ*NCH*PQ*NSQ];         // chunk-final local state [blk][n][p]
static __device__ float g_Hs [BQ*HQ*NCH*PQ*NSQ];         // chunk-START state H0   [blk][n][p]
static __device__ float g_pool[BQ*DQ];

__device__ __forceinline__ float geluf(float x){
    return 0.5f * x * (1.0f + erff(x * 0.7071067811865476f));
}

// ---------------- embedding ----------------
__global__ void k_embed(const int* __restrict__ ids, const float* __restrict__ emb,
                        const float* __restrict__ pos){
    int row = blockIdx.x;            // b*LQ + l
    int l   = row & (LQ-1);
    int d   = threadIdx.x;
    g_x[(size_t)row*DQ + d] = emb[(size_t)ids[row]*DQ + d] + pos[(size_t)l*DQ + d];
}

// ================= GEMM 128x64 (FMA2, prefetch-pipelined): C[m,n]=sum_k A[m,k]B[n,k] ==
template<int M, int N, int K, bool ACC>
__device__ __forceinline__ void gemm128(const float* __restrict__ A,
                                        const float* __restrict__ Bw,
                                        float* __restrict__ Cc){
    constexpr int BM=128, BN=64, BK=16;
    __shared__ __align__(16) float As[2][BK][BM];
    __shared__ __align__(16) float Bs[2][BK][BN];
    const int tid = threadIdx.x;
    const int bm  = blockIdx.y * BM;
    const int bn  = blockIdx.x * BN;
    const int alr = tid & 127;
    const int alc = (tid >> 7) * 8;
    const int blr = tid & 63;
    const int blc = (tid >> 6) * 4;
    const int tr  = (tid >> 4) * 8;    // m-offset (8 rows = 4 pairs)
    const int tc  = (tid & 15) * 4;    // n-offset (4 cols)

    const bool bvalid = (N % BN == 0) || (bn + blr < N);
    const float* Aptr = A  + (size_t)(bm + alr)*K + alc;
    const float* Bptr = Bw + (size_t)(bn + blr)*K + blc;

    u64 accp[4][4];                    // [m-pair][n]
    #pragma unroll
    for (int m=0;m<4;m++)
        #pragma unroll
        for (int n=0;n<4;n++) accp[m][n]=0ull;

    float4 ra0, ra1, rb0;
    auto ldg = [&](int k0){
        ra0 = *(const float4*)(Aptr + k0);
        ra1 = *(const float4*)(Aptr + k0 + 4);
        rb0 = make_float4(0.f,0.f,0.f,0.f);
        if (bvalid) rb0 = *(const float4*)(Bptr + k0);
    };
    auto sts = [&](int buf){
        As[buf][alc+0][alr]=ra0.x; As[buf][alc+1][alr]=ra0.y;
        As[buf][alc+2][alr]=ra0.z; As[buf][alc+3][alr]=ra0.w;
        As[buf][alc+4][alr]=ra1.x; As[buf][alc+5][alr]=ra1.y;
        As[buf][alc+6][alr]=ra1.z; As[buf][alc+7][alr]=ra1.w;
        Bs[buf][blc+0][blr]=rb0.x; Bs[buf][blc+1][blr]=rb0.y;
        Bs[buf][blc+2][blr]=rb0.z; Bs[buf][blc+3][blr]=rb0.w;
    };

    ldg(0); sts(0);
    __syncthreads();
    constexpr int NK = K/BK;
    #pragma unroll 1
    for (int kt=0; kt<NK; kt++){
        if (kt+1 < NK) ldg((kt+1)*BK);
        const int cur = kt & 1;
        #pragma unroll
        for (int kk=0; kk<BK; kk++){
            u64 a0 = *(const u64*)&As[cur][kk][tr];
            u64 a1 = *(const u64*)&As[cur][kk][tr+2];
            u64 a2 = *(const u64*)&As[cur][kk][tr+4];
            u64 a3 = *(const u64*)&As[cur][kk][tr+6];
            float4 b = *(const float4*)&Bs[cur][kk][tc];
            u64 b0 = pk2(b.x,b.x), b1 = pk2(b.y,b.y), b2 = pk2(b.z,b.z), b3 = pk2(b.w,b.w);
            accp[0][0]=fma2(a0,b0,accp[0][0]); accp[0][1]=fma2(a0,b1,accp[0][1]);
            accp[0][2]=fma2(a0,b2,accp[0][2]); accp[0][3]=fma2(a0,b3,accp[0][3]);
            accp[1][0]=fma2(a1,b0,accp[1][0]); accp[1][1]=fma2(a1,b1,accp[1][1]);
            accp[1][2]=fma2(a1,b2,accp[1][2]); accp[1][3]=fma2(a1,b3,accp[1][3]);
            accp[2][0]=fma2(a2,b0,accp[2][0]); accp[2][1]=fma2(a2,b1,accp[2][1]);
            accp[2][2]=fma2(a2,b2,accp[2][2]); accp[2][3]=fma2(a2,b3,accp[2][3]);
            accp[3][0]=fma2(a3,b0,accp[3][0]); accp[3][1]=fma2(a3,b1,accp[3][1]);
            accp[3][2]=fma2(a3,b2,accp[3][2]); accp[3][3]=fma2(a3,b3,accp[3][3]);
        }
        if (kt+1 < NK) sts((kt+1) & 1);
        __syncthreads();
    }
    const int col0 = bn + tc;
    const bool cvalid = (N % BN == 0) || (col0 < N);
    #pragma unroll
    for (int mp=0; mp<4; mp++){
        float4 lo, hi;
        upk2(lo.x, hi.x, accp[mp][0]);
        upk2(lo.y, hi.y, accp[mp][1]);
        upk2(lo.z, hi.z, accp[mp][2]);
        upk2(lo.w, hi.w, accp[mp][3]);
        if (cvalid){
            size_t i0 = (size_t)(bm + tr + 2*mp)*N + col0;
            size_t i1 = i0 + N;
            if (ACC){
                float4 c0 = *(float4*)&Cc[i0];
                float4 c1 = *(float4*)&Cc[i1];
                c0.x+=lo.x; c0.y+=lo.y; c0.z+=lo.z; c0.w+=lo.w;
                c1.x+=hi.x; c1.y+=hi.y; c1.z+=hi.z; c1.w+=hi.w;
                *(float4*)&Cc[i0] = c0;
                *(float4*)&Cc[i1] = c1;
            } else {
                *(float4*)&Cc[i0] = lo;
                *(float4*)&Cc[i1] = hi;
            }
        }
    }
}

// ================= GEMM 64x64 (FMA2, prefetch-pipelined) =================
template<int M, int N, int K, bool ACC>
__device__ __forceinline__ void gemm64(const float* __restrict__ A,
                                       const float* __restrict__ Bw,
                                       float* __restrict__ Cc){
    constexpr int BM=64, BN=64, BK=16;
    __shared__ __align__(16) float As[2][BK][BM];
    __shared__ __align__(16) float Bs[2][BK][BN];
    const int tid = threadIdx.x;
    const int bm  = blockIdx.y * BM;
    const int bn  = blockIdx.x * BN;
    const int lr  = tid & 63;
    const int lc  = (tid >> 6) * 4;
    const int tr  = (tid >> 4) * 4;    // 4 rows = 2 pairs
    const int tc  = (tid & 15) * 4;

    const bool bvalid = (N % BN == 0) || (bn + lr < N);
    const float* Aptr = A  + (size_t)(bm + lr)*K + lc;
    const float* Bptr = Bw + (size_t)(bn + lr)*K + lc;

    u64 accp[2][4];
    #pragma unroll
    for (int m=0;m<2;m++)
        #pragma unroll
        for (int n=0;n<4;n++) accp[m][n]=0ull;

    float4 ra, rb;
    auto ldg = [&](int k0){
        ra = *(const float4*)(Aptr + k0);
        rb = make_float4(0.f,0.f,0.f,0.f);
        if (bvalid) rb = *(const float4*)(Bptr + k0);
    };
    auto sts = [&](int buf){
        As[buf][lc+0][lr]=ra.x; As[buf][lc+1][lr]=ra.y;
        As[buf][lc+2][lr]=ra.z; As[buf][lc+3][lr]=ra.w;
        Bs[buf][lc+0][lr]=rb.x; Bs[buf][lc+1][lr]=rb.y;
        Bs[buf][lc+2][lr]=rb.z; Bs[buf][lc+3][lr]=rb.w;
    };

    ldg(0); sts(0);
    __syncthreads();
    constexpr int NK = K/BK;
    #pragma unroll 1
    for (int kt=0; kt<NK; kt++){
        if (kt+1 < NK) ldg((kt+1)*BK);
        const int cur = kt & 1;
        #pragma unroll
        for (int kk=0; kk<BK; kk++){
            u64 a0 = *(const u64*)&As[cur][kk][tr];
            u64 a1 = *(const u64*)&As[cur][kk][tr+2];
            float4 b = *(const float4*)&Bs[cur][kk][tc];
            u64 b0 = pk2(b.x,b.x), b1 = pk2(b.y,b.y), b2 = pk2(b.z,b.z), b3 = pk2(b.w,b.w);
            accp[0][0]=fma2(a0,b0,accp[0][0]); accp[0][1]=fma2(a0,b1,accp[0][1]);
            accp[0][2]=fma2(a0,b2,accp[0][2]); accp[0][3]=fma2(a0,b3,accp[0][3]);
            accp[1][0]=fma2(a1,b0,accp[1][0]); accp[1][1]=fma2(a1,b1,accp[1][1]);
            accp[1][2]=fma2(a1,b2,accp[1][2]); accp[1][3]=fma2(a1,b3,accp[1][3]);
        }
        if (kt+1 < NK) sts((kt+1) & 1);
        __syncthreads();
    }
    const int col0 = bn + tc;
    const bool cvalid = (N % BN == 0) || (col0 < N);
    #pragma unroll
    for (int mp=0; mp<2; mp++){
        float4 lo, hi;
        upk2(lo.x, hi.x, accp[mp][0]);
        upk2(lo.y, hi.y, accp[mp][1]);
        upk2(lo.z, hi.z, accp[mp][2]);
        upk2(lo.w, hi.w, accp[mp][3]);
        if (cvalid){
            size_t i0 = (size_t)(bm + tr + 2*mp)*N + col0;
            size_t i1 = i0 + N;
            if (ACC){
                float4 c0 = *(float4*)&Cc[i0];
                float4 c1 = *(float4*)&Cc[i1];
                c0.x+=lo.x; c0.y+=lo.y; c0.z+=lo.z; c0.w+=lo.w;
                c1.x+=hi.x; c1.y+=hi.y; c1.z+=hi.z; c1.w+=hi.w;
                *(float4*)&Cc[i0] = c0;
                *(float4*)&Cc[i1] = c1;
            } else {
                *(float4*)&Cc[i0] = lo;
                *(float4*)&Cc[i1] = hi;
            }
        }
    }
}

__global__ __launch_bounds__(256) void k_gemm_in(const float* __restrict__ W){
    gemm128<BQ*LQ, DPROJ, DQ, false>(g_x, W, g_zx);
}
__global__ __launch_bounds__(256) void k_gemm_out(const float* __restrict__ W){
    gemm64<BQ*LQ, DQ, DINQ, true>(g_y, W, g_x);
}

// ---------------- depthwise causal conv + SiLU, and dt ----------------
__global__ void k_convdt(const float* __restrict__ cw, const float* __restrict__ cb,
                         const float* __restrict__ dtb){
    int row = blockIdx.x;            // b*LQ + l
    int l   = row & (LQ-1);
    int ci  = threadIdx.x;           // 0..639
    float4 w = *(const float4*)(cw + ci*4);   // conv_w[ci][0..3]
    const float* src = g_zx + (size_t)row*DPROJ + DINQ + ci;
    float acc = cb[ci];
    acc = fmaf(w.w, src[0], acc);
    if (l >= 1) acc = fmaf(w.z, src[-DPROJ],   acc);
    if (l >= 2) acc = fmaf(w.y, src[-2*DPROJ], acc);
    if (l >= 3) acc = fmaf(w.x, src[-3*DPROJ], acc);
    g_xBC[(size_t)row*CONVD + ci] = acc / (1.f + expf(-acc));   // SiLU
    if (ci < HQ){
        float raw = g_zx[(size_t)row*DPROJ + (DINQ + CONVD) + ci] + dtb[ci];
        float dt  = (raw > 20.f) ? raw : log1pf(expf(raw));     // softplus
        g_dt[(size_t)row*HQ + ci] = dt;
    }
}

// ---------------- S1: per-chunk local final state F[n][p] (+ fused warp-scan) ---------
// float4 load phase (row-major smem, conflict-free); coalesced float4 F stores
__global__ __launch_bounds__(256) void k_state(const float* __restrict__ Alog){
    const int blk = blockIdx.x;
    const int c   = blk & (NCH-1);
    const int bh  = blk >> 5;
    const int h   = bh & (HQ-1);
    const int b   = bh >> 3;
    const int tid = threadIdx.x;
    const int t0  = c*LC;

    __shared__ __align__(16) float sX[LC][PQ];
    __shared__ __align__(16) float sB[LC][NSQ];
    __shared__ float sW[LC];

    // 4096 floats = LC rows x (64 X + 64 B), as 1024 float4s (4 per thread)
    #pragma unroll
    for (int it=0; it<4; it++){
        int idx = tid + it*256;
        int s   = idx >> 5;            // row 0..31
        int q4  = idx & 31;            // float4 slot within row
        const float* rowp = g_xBC + (size_t)(b*LQ + t0 + s)*CONVD;
        if (q4 < 16) *(float4*)&sX[s][q4*4]      = *(const float4*)(rowp + h*PQ + q4*4);
        else         *(float4*)&sB[s][(q4-16)*4] = *(const float4*)(rowp + DINQ + (q4-16)*4);
    }
    if (tid < 32){   // chunk-local inclusive cumsum of dt*|A| via warp scan
        float dts  = g_dt[(size_t)(b*LQ + t0 + tid)*HQ + h];
        float v = dts * expf(Alog[h]);
        #pragma unroll
        for (int o=1; o<32; o<<=1){
            float u = __shfl_up_sync(0xffffffffu, v, o);
            if (tid >= o) v += u;
        }
        float Sl = __shfl_sync(0xffffffffu, v, 31);
        sW[tid] = expf(v - Sl) * dts;
        if (tid == 31) g_slast[blk] = v;
    }
    __syncthreads();

    const int p0 = (tid & 15) * 4;     // p contiguous across lanes
    const int n0 = (tid >> 4) * 4;     // n broadcast within half-warp
    u64 fp[2][4];                       // [p-pair][n]
    #pragma unroll
    for (int i=0;i<2;i++)
        #pragma unroll
        for (int j=0;j<4;j++) fp[i][j]=0ull;

    #pragma unroll 4
    for (int s=0; s<LC; s++){
        u64 x01 = *(const u64*)&sX[s][p0];
        u64 x23 = *(const u64*)&sX[s][p0+2];
        float4 bv = *(const float4*)&sB[s][n0];
        float w = sW[s];
        u64 w2 = pk2(w,w);
        u64 wx01 = mul2(x01, w2);
        u64 wx23 = mul2(x23, w2);
        u64 b0 = pk2(bv.x,bv.x), b1 = pk2(bv.y,bv.y), b2 = pk2(bv.z,bv.z), b3 = pk2(bv.w,bv.w);
        fp[0][0]=fma2(wx01,b0,fp[0][0]); fp[1][0]=fma2(wx23,b0,fp[1][0]);
        fp[0][1]=fma2(wx01,b1,fp[0][1]); fp[1][1]=fma2(wx23,b1,fp[1][1]);
        fp[0][2]=fma2(wx01,b2,fp[0][2]); fp[1][2]=fma2(wx23,b2,fp[1][2]);
        fp[0][3]=fma2(wx01,b3,fp[0][3]); fp[1][3]=fma2(wx23,b3,fp[1][3]);
    }
    float* Fo = g_F + (size_t)blk*(PQ*NSQ);
    #pragma unroll
    for (int j=0;j<4;j++){
        float4 v;
        upk2(v.x, v.y, fp[0][j]);
        upk2(v.z, v.w, fp[1][j]);
        *(float4*)&Fo[(size_t)(n0+j)*PQ + p0] = v;   // lanes contiguous in p -> coalesced
    }
}

// ---------------- chain chunk-start states: one thread per element, MLP=32 -----------
__global__ __launch_bounds__(256) void k_combine(){
    const int blk = blockIdx.x;              // 0..255 (16 per bh)
    const int bh  = blk >> 4;
    const int e   = (blk & 15)*256 + threadIdx.x;   // element 0..4095
    __shared__ float sP[NCH];
    if (threadIdx.x < NCH) sP[threadIdx.x] = expf(-g_slast[bh*NCH + threadIdx.x]);
    __syncthreads();
    const float* Fp = g_F  + (size_t)bh*NCH*(PQ*NSQ) + e;
    float*       Hp = g_Hs + (size_t)bh*NCH*(PQ*NSQ) + e;
    float f[NCH];
    #pragma unroll
    for (int c=0; c<NCH; c++) f[c] = Fp[(size_t)c*(PQ*NSQ)];   // 32 independent coalesced LDGs
    float hs = 0.f;
    #pragma unroll
    for (int c=0; c<NCH; c++){
        Hp[(size_t)c*(PQ*NSQ)] = hs;
        hs = fmaf(sP[c], hs, f[c]);
    }
}

// ---------------- S2: full chunk output via dense matmuls (FMA2) ---------------------
// y[t][p] = sum_{s<=t} exp(S_s-S_t)*dt_s*(C_t.B_s)*x_s[p] + exp(-S_t)*(C_t.H0)[p] + D*x_t[p]
#define PADT 36
__global__ __launch_bounds__(256) void k_out(const float* __restrict__ Dparam,
                                             const float* __restrict__ Alog){
    const int blk = blockIdx.x;
    const int c   = blk & (NCH-1);
    const int bh  = blk >> 5;
    const int h   = bh & (HQ-1);
    const int b   = bh >> 3;
    const int tid = threadIdx.x;
    const int t0  = c*LC;

    __shared__ __align__(16) float sX [LC][PQ];     // [s][p]
    __shared__ __align__(16) float sBT[NSQ][PADT];  // [n][s]
    __shared__ __align__(16) float sCT[NSQ][PADT];  // [n][t]
    __shared__ __align__(16) float sM [LC][PADT];   // [s][t]
    __shared__ __align__(16) float sH [NSQ][PQ];    // [n][p]
    __shared__ float sS[LC], sDt[LC], sA[LC];

    // X: 512 float4s, coalesced, conflict-free
    #pragma unroll
    for (int it=0; it<2; it++){
        int idx = tid + it*256;
        int s = idx >> 4, q4 = idx & 15;
        *(float4*)&sX[s][q4*4] = *(const float4*)(g_xBC + (size_t)(b*LQ + t0 + s)*CONVD + h*PQ + q4*4);
    }
    // B/C transposed scatter (scalar STS; vector STS would worsen bank conflicts)
    for (int idx=tid; idx<LC*64; idx+=256){
        int s = idx >> 6, j = idx & 63;
        const float* rowp = g_xBC + (size_t)(b*LQ + t0 + s)*CONVD + DINQ;
        sBT[j][s] = rowp[j];
        sCT[j][s] = rowp[NSQ + j];
    }
    {   // H0: 1024 float4s, coalesced
        const float* Hi = g_Hs + (size_t)blk*(PQ*NSQ);
        #pragma unroll
        for (int it=0; it<4; it++){
            int idx = tid + it*256;
            *(float4*)&sH[0][idx*4] = *(const float4*)(Hi + idx*4);
        }
    }
    if (tid < 32){   // fused chunk-local warp scan
        float dts = g_dt[(size_t)(b*LQ + t0 + tid)*HQ + h];
        sDt[tid] = dts;
        float v = dts * expf(Alog[h]);
        #pragma unroll
        for (int o=1; o<32; o<<=1){
            float u = __shfl_up_sync(0xffffffffu, v, o);
            if (tid >= o) v += u;
        }
        sS[tid] = v;
        sA[tid] = expf(-v);
    }
    __syncthreads();

    // ---- stage b: G = C @ B^T, then decay+mask -> M_T[s][t] ----
    {
        const int tG = tid >> 3;            // 0..31  (t index)
        const int s0 = (tid & 7) * 4;       // 0..28  (s group, 2 pairs)
        u64 g01 = 0ull, g23 = 0ull;
        #pragma unroll 8
        for (int n=0; n<NSQ; n++){
            float cv = sCT[n][tG];
            u64 cv2 = pk2(cv, cv);
            u64 b01 = *(const u64*)&sBT[n][s0];
            u64 b23 = *(const u64*)&sBT[n][s0+2];
            g01 = fma2(cv2, b01, g01);
            g23 = fma2(cv2, b23, g23);
        }
        float gx, gy, gz, gw;
        upk2(gx, gy, g01);
        upk2(gz, gw, g23);
        float St = sS[tG];
        sM[s0+0][tG] = (s0+0 <= tG) ? gx * expf(sS[s0+0] - St) * sDt[s0+0] : 0.f;
        sM[s0+1][tG] = (s0+1 <= tG) ? gy * expf(sS[s0+1] - St) * sDt[s0+1] : 0.f;
        sM[s0+2][tG] = (s0+2 <= tG) ? gz * expf(sS[s0+2] - St) * sDt[s0+2] : 0.f;
        sM[s0+3][tG] = (s0+3 <= tG) ? gw * expf(sS[s0+3] - St) * sDt[s0+3] : 0.f;
    }
    __syncthreads();

    // ---- stages c+d: Y1 = M @ X ; Ycorr = C @ H0 ; packed epilogue ----
    {
        const int tr = (tid >> 4) * 2;      // rows t = tr, tr+1
        const int pc = (tid & 15) * 4;      // 4 p = 2 pairs
        u64 y0a=0ull, y0b=0ull, y1a=0ull, y1b=0ull;
        #pragma unroll 8
        for (int s=0; s<LC; s++){
            float m0 = sM[s][tr], m1 = sM[s][tr+1];
            u64 x01 = *(const u64*)&sX[s][pc];
            u64 x23 = *(const u64*)&sX[s][pc+2];
            u64 m02 = pk2(m0,m0), m12 = pk2(m1,m1);
            y0a = fma2(m02, x01, y0a); y0b = fma2(m02, x23, y0b);
            y1a = fma2(m12, x01, y1a); y1b = fma2(m12, x23, y1b);
        }
        u64 c0a=0ull, c0b=0ull, c1a=0ull, c1b=0ull;
        #pragma unroll 8
        for (int n=0; n<NSQ; n++){
            float c0 = sCT[n][tr], c1 = sCT[n][tr+1];
            u64 h01 = *(const u64*)&sH[n][pc];
            u64 h23 = *(const u64*)&sH[n][pc+2];
            u64 c02 = pk2(c0,c0), c12 = pk2(c1,c1);
            c0a = fma2(c02, h01, c0a); c0b = fma2(c02, h23, c0b);
            c1a = fma2(c12, h01, c1a); c1b = fma2(c12, h23, c1b);
        }
        const float Dv = Dparam[h];
        const u64 Dv2 = pk2(Dv, Dv);
        {
            u64 at2 = pk2(sA[tr], sA[tr]);
            u64 x01 = *(const u64*)&sX[tr][pc];
            u64 x23 = *(const u64*)&sX[tr][pc+2];
            u64 o01 = fma2(at2, c0a, y0a); o01 = fma2(Dv2, x01, o01);
            u64 o23 = fma2(at2, c0b, y0b); o23 = fma2(Dv2, x23, o23);
            float4 o; upk2(o.x, o.y, o01); upk2(o.z, o.w, o23);
            *(float4*)&g_y[(size_t)(b*LQ + t0 + tr)*DINQ + h*PQ + pc] = o;
        }
        {
            u64 at2 = pk2(sA[tr+1], sA[tr+1]);
            u64 x01 = *(const u64*)&sX[tr+1][pc];
            u64 x23 = *(const u64*)&sX[tr+1][pc+2];
            u64 o01 = fma2(at2, c1a, y1a); o01 = fma2(Dv2, x01, o01);
            u64 o23 = fma2(at2, c1b, y1b); o23 = fma2(Dv2, x23, o23);
            float4 o; upk2(o.x, o.y, o01); upk2(o.z, o.w, o23);
            *(float4*)&g_y[(size_t)(b*LQ + t0 + tr + 1)*DINQ + h*PQ + pc] = o;
        }
    }
}

// ---------------- gate (SiLU(z)) + RMSNorm ----------------
__global__ __launch_bounds__(512) void k_gatenorm(const float* __restrict__ nw){
    int row = blockIdx.x;
    int tid = threadIdx.x;
    float y = g_y[(size_t)row*DINQ + tid];
    float z = g_zx[(size_t)row*DPROJ + tid];
    float v = y * (z / (1.f + expf(-z)));
    float ss = v*v;
    #pragma unroll
    for (int o=16;o;o>>=1) ss += __shfl_xor_sync(0xffffffffu, ss, o);
    __shared__ float red[16];
    if ((tid & 31) == 0) red[tid>>5] = ss;
    __syncthreads();
    if (tid < 32){
        float t = (tid < 16) ? red[tid] : 0.f;
        #pragma unroll
        for (int o=8;o;o>>=1) t += __shfl_xor_sync(0xffffffffu, t, o);
        if (tid == 0) red[0] = t;
    }
    __syncthreads();
    float r = rsqrtf(red[0]*(1.f/DINQ) + 1e-5f);
    g_y[(size_t)row*DINQ + tid] = v * r * nw[tid];
}

// ---------------- pooling: (mean_l + max_l) * 0.5 ----------------
__global__ void k_pool(){
    int b = blockIdx.x, d = threadIdx.x;
    const float* base = g_x + (size_t)b*LQ*DQ + d;
    float s = 0.f, m = -3.4e38f;
    #pragma unroll 8
    for (int l=0; l<LQ; l++){
        float v = base[(size_t)l*DQ];
        s += v; m = fmaxf(m, v);
    }
    g_pool[b*DQ + d] = (s*(1.f/LQ) + m)*0.5f;
}

// ---------------- classification head (single block) ----------------
__global__ __launch_bounds__(256) void k_head(const float* __restrict__ pw, const float* __restrict__ pb,
                                              const float* __restrict__ c1w, const float* __restrict__ c1b,
                                              const float* __restrict__ c2w, const float* __restrict__ c2b,
                                              float* __restrict__ out){
    __shared__ __align__(16) float sp[BQ*DQ];
    __shared__ __align__(16) float h1[BQ*DQ];
    __shared__ __align__(16) float h2[BQ*128];
    int tid = threadIdx.x;
    for (int i=tid; i<BQ*DQ; i+=256) sp[i] = g_pool[i];
    __syncthreads();
    for (int i=tid; i<BQ*DQ; i+=256){
        int b = i >> 8, o = i & 255;
        const float4* xr = (const float4*)(sp + b*DQ);
        const float4* wr = (const float4*)(pw + (size_t)o*DQ);
        float a = pb[o];
        #pragma unroll 8
        for (int k=0; k<DQ/4; k++){
            float4 xv = xr[k], wv = wr[k];
            a = fmaf(xv.x,wv.x,a); a = fmaf(xv.y,wv.y,a);
            a = fmaf(xv.z,wv.z,a); a = fmaf(xv.w,wv.w,a);
        }
        h1[i] = geluf(a);
    }
    __syncthreads();
    {
        int b = tid >> 7, o = tid & 127;
        const float4* xr = (const float4*)(h1 + b*DQ);
        const float4* wr = (const float4*)(c1w + (size_t)o*DQ);
        float a = c1b[o];
        #pragma unroll 8
        for (int k=0; k<DQ/4; k++){
            float4 xv = xr[k], wv = wr[k];
            a = fmaf(xv.x,wv.x,a); a = fmaf(xv.y,wv.y,a);
            a = fmaf(xv.z,wv.z,a); a = fmaf(xv.w,wv.w,a);
        }
        h2[tid] = geluf(a);
    }
    __syncthreads();
    if (tid < 4){
        int b = tid >> 1, o = tid & 1;
        const float* xr = h2 + b*128;
        const float* wr = c2w + o*128;
        float a = c2b[o];
        #pragma unroll 8
        for (int k=0; k<128; k++) a = fmaf(xr[k], wr[k], a);
        out[b*2 + o] = a;
    }
}

// ---------------- launcher ----------------
extern "C" void kernel_launch(void* const* d_in, const int* in_sizes, int n_in,
                              void* d_out, int out_size){
    (void)in_sizes; (void)n_in; (void)out_size;
    const int*   ids  = (const int*)  d_in[0];
    const float* emb  = (const float*)d_in[1];
    const float* pos  = (const float*)d_in[2];
    const float* Win  = (const float*)d_in[3];
    const float* cw   = (const float*)d_in[4];
    const float* cb   = (const float*)d_in[5];
    const float* dtb  = (const float*)d_in[6];
    const float* Alog = (const float*)d_in[7];
    const float* Dpar = (const float*)d_in[8];
    const float* nw   = (const float*)d_in[9];
    const float* Wout = (const float*)d_in[10];
    const float* pw   = (const float*)d_in[11];
    const float* pb   = (const float*)d_in[12];
    const float* c1w  = (const float*)d_in[13];
    const float* c1b  = (const float*)d_in[14];
    const float* c2w  = (const float*)d_in[15];
    const float* c2b  = (const float*)d_in[16];
    float* out = (float*)d_out;

    k_embed<<<BQ*LQ, DQ>>>(ids, emb, pos);
    for (int i=0; i<NLQ; i++){
        k_gemm_in <<<dim3((DPROJ+63)/64, (BQ*LQ)/128), 256>>>(Win + (size_t)i*DPROJ*DQ);
        k_convdt  <<<BQ*LQ, CONVD>>>(cw + (size_t)i*CONVD*4, cb + (size_t)i*CONVD,
                                     dtb + (size_t)i*HQ);
        k_state   <<<BQ*HQ*NCH, 256>>>(Alog + (size_t)i*HQ);
        k_combine <<<BQ*HQ*16, 256>>>();
        k_out     <<<BQ*HQ*NCH, 256>>>(Dpar + (size_t)i*HQ, Alog + (size_t)i*HQ);
        k_gatenorm<<<BQ*LQ, DINQ>>>(nw + (size_t)i*DINQ);
        k_gemm_out<<<dim3(DQ/64, (BQ*LQ)/64), 256>>>(Wout + (size_t)i*DQ*DINQ);
    }
    k_pool<<<BQ, DQ>>>();
    k_head<<<1, 256>>>(pw, pb, c1w, c1b, c2w, c2b, out);
}